// round 5
// baseline (speedup 1.0000x reference)
#include <cuda_runtime.h>
#include <cuda_bf16.h>

#define NB 32
#define NS 1024
#define ND 256

// ---------------- packed f32x2 helpers --------------------------------------
__device__ __forceinline__ void FMA2(unsigned long long& d, unsigned long long a,
                                     unsigned long long b) {
    asm("fma.rn.f32x2 %0, %1, %2, %0;" : "+l"(d) : "l"(a), "l"(b));
}
__device__ __forceinline__ unsigned long long MUL2(unsigned long long a,
                                                   unsigned long long b) {
    unsigned long long d;
    asm("mul.rn.f32x2 %0, %1, %2;" : "=l"(d) : "l"(a), "l"(b));
    return d;
}
__device__ __forceinline__ unsigned long long splat2(float v) {
    unsigned long long r;
    asm("mov.b64 %0, {%1, %1};" : "=l"(r) : "f"(v));
    return r;
}
__device__ __forceinline__ unsigned long long pack2(float x, float y) {
    unsigned long long r;
    asm("mov.b64 %0, {%1, %2};" : "=l"(r) : "f"(x), "f"(y));
    return r;
}
__device__ __forceinline__ float2 u2f(unsigned long long v) {
    float2 r;
    asm("mov.b64 {%0, %1}, %2;" : "=f"(r.x), "=f"(r.y) : "l"(v));
    return r;
}

// ---------------- scratch (static __device__, no allocation) ----------------
__device__ __align__(16) float g_M[ND][ND];     // M[d][e] = sum_a Wq[a][d]*Wk[a][e]
__device__ __align__(16) float g_vecA[ND];      // Wq^T bk
__device__ __align__(16) float g_vecB[ND];      // Wk^T bq
__device__ float g_c;                           // bq . bk
__device__ int   g_sw_idx[NB][NS];
__device__ int   g_dr_idx[NB][NS];
__device__ int   g_nsw[NB];
__device__ int   g_ndr[NB];
__device__ __align__(16) float g_partAll[NB][4][ND];
__device__ __align__(16) float g_partDoor[NB][4][ND];
__device__ __align__(16) float g_uc[NB][NS];    // cw*(x_t . vecB) per door slot
__device__ __align__(16) float g_vc[NB][NS];    // cw*(x_s . vecA + c) per switch slot
__device__ __align__(16) float g_z[NB][NS][ND]; // cw*(x_s . M) per switch slot

// ---------------- K_M: M = Wq^T Wk (32x32 tiles) + bias vectors + c ---------
__global__ void __launch_bounds__(256) k_M(const float* __restrict__ Wq,
                                           const float* __restrict__ Wk,
                                           const float* __restrict__ bq,
                                           const float* __restrict__ bk) {
    int tid = threadIdx.x;
    if (blockIdx.x == 64) {
        int d = tid;
        float va = 0.f, vb = 0.f;
        #pragma unroll 8
        for (int a = 0; a < ND; a++) {
            va += Wq[a * ND + d] * bk[a];
            vb += Wk[a * ND + d] * bq[a];
        }
        g_vecA[d] = va;
        g_vecB[d] = vb;
        if (tid < 32) {
            float c = 0.f;
            for (int i = tid; i < ND; i += 32) c += bq[i] * bk[i];
            #pragma unroll
            for (int o = 16; o; o >>= 1) c += __shfl_down_sync(0xFFFFFFFFu, c, o);
            if (tid == 0) g_c = c;
        }
        return;
    }
    int dt = blockIdx.x >> 3, et = blockIdx.x & 7;
    __shared__ float As[16][32], Bs[16][32];
    float a00 = 0.f, a01 = 0.f, a10 = 0.f, a11 = 0.f;
    int dg = tid >> 4, eg = tid & 15;
    int al = tid >> 4, c2 = (tid & 15) * 2;
    for (int a0 = 0; a0 < ND; a0 += 16) {
        *(float2*)&As[al][c2] = *(const float2*)&Wq[(a0 + al) * ND + dt * 32 + c2];
        *(float2*)&Bs[al][c2] = *(const float2*)&Wk[(a0 + al) * ND + et * 32 + c2];
        __syncthreads();
        #pragma unroll
        for (int k = 0; k < 16; k++) {
            float2 av = *(const float2*)&As[k][dg * 2];
            float2 bv = *(const float2*)&Bs[k][eg * 2];
            a00 += av.x * bv.x; a01 += av.x * bv.y;
            a10 += av.y * bv.x; a11 += av.y * bv.y;
        }
        __syncthreads();
    }
    int d = dt * 32 + dg * 2, e = et * 32 + eg * 2;
    g_M[d][e]     = a00; g_M[d][e + 1]     = a01;
    g_M[d + 1][e] = a10; g_M[d + 1][e + 1] = a11;
}

// ---------------- K_prep: dtype detect + masks + bias dots | colsum ---------
__global__ void __launch_bounds__(1024) k_prep(const int* __restrict__ s32,
                                               const float* __restrict__ emb,
                                               const float* __restrict__ cwp) {
    int b = blockIdx.x, bz = blockIdx.y, tid = threadIdx.x;
    // int64 vs int32: odd int32 words in [b*NS,(b+1)*NS) are all 0 iff int64.
    int vdet = (tid < 512) ? s32[b * NS + 2 * tid + 1] : 0;
    int is64 = !__syncthreads_or(vdet != 0);

    if (bz == 0) {
        int t = tid;
        int st = is64 ? s32[2 * (b * NS + t)] : s32[b * NS + t];
        int isw = (st == 3), idr = (st == 4 || st == 5);
        unsigned mw = __ballot_sync(0xFFFFFFFFu, isw);
        unsigned md = __ballot_sync(0xFFFFFFFFu, idr);
        int lane = t & 31, w = t >> 5;
        __shared__ int cw_[32], cd_[32], ow_[32], od_[32], snsw, sndr;
        if (lane == 0) { cw_[w] = __popc(mw); cd_[w] = __popc(md); }
        __syncthreads();
        if (tid == 0) {
            int aw = 0, ad = 0;
            for (int i = 0; i < 32; i++) {
                ow_[i] = aw; aw += cw_[i];
                od_[i] = ad; ad += cd_[i];
            }
            g_nsw[b] = aw; g_ndr[b] = ad; snsw = aw; sndr = ad;
        }
        __syncthreads();
        if (isw) g_sw_idx[b][ow_[w] + __popc(mw & ((1u << lane) - 1u))] = t;
        if (idr) g_dr_idx[b][od_[w] + __popc(md & ((1u << lane) - 1u))] = t;
        __syncthreads();
        float cwv = *cwp, cval = g_c;
        int nd = sndr, nw2 = snsw;
        for (int slot = w; slot < nd; slot += 32) {
            int tt = g_dr_idx[b][slot];
            const float4* er = (const float4*)&emb[((size_t)b * NS + tt) * ND];
            const float4* vr = (const float4*)g_vecB;
            float s = 0.f;
            #pragma unroll
            for (int j2 = 0; j2 < 2; j2++) {
                float4 e4 = er[lane + 32 * j2], v4 = vr[lane + 32 * j2];
                s += e4.x * v4.x + e4.y * v4.y + e4.z * v4.z + e4.w * v4.w;
            }
            #pragma unroll
            for (int o = 16; o; o >>= 1) s += __shfl_down_sync(0xFFFFFFFFu, s, o);
            if (lane == 0) g_uc[b][slot] = cwv * s;
        }
        for (int slot = w; slot < nw2; slot += 32) {
            int tt = g_sw_idx[b][slot];
            const float4* er = (const float4*)&emb[((size_t)b * NS + tt) * ND];
            const float4* vr = (const float4*)g_vecA;
            float s = 0.f;
            #pragma unroll
            for (int j2 = 0; j2 < 2; j2++) {
                float4 e4 = er[lane + 32 * j2], v4 = vr[lane + 32 * j2];
                s += e4.x * v4.x + e4.y * v4.y + e4.z * v4.z + e4.w * v4.w;
            }
            #pragma unroll
            for (int o = 16; o; o >>= 1) s += __shfl_down_sync(0xFFFFFFFFu, s, o);
            if (lane == 0) g_vc[b][slot] = cwv * (s + cval);
        }
    } else {
        int c = bz - 1, tg = tid >> 8, d = tid & 255;
        float sa = 0.f, sd = 0.f;
        int tb = c * 256 + tg * 64;
        #pragma unroll 4
        for (int i = 0; i < 64; i++) {
            int t = tb + i;
            float v = emb[((size_t)b * NS + t) * ND + d];
            int st = is64 ? s32[2 * (b * NS + t)] : s32[b * NS + t];
            sa += v;
            if (st == 4 || st == 5) sd += v;
        }
        __shared__ float psA[4][ND], psD[4][ND];
        psA[tg][d] = sa; psD[tg][d] = sd;
        __syncthreads();
        if (tid < ND) {
            float a = 0.f, dd = 0.f;
            #pragma unroll
            for (int g = 0; g < 4; g++) { a += psA[g][tid]; dd += psD[g][tid]; }
            g_partAll[b][c][tid]  = a;
            g_partDoor[b][c][tid] = dd;
        }
    }
}

// ---------------- K_default: out = emb + 0.5*colMean (all rows) -------------
__global__ void __launch_bounds__(256) k_default(const float* __restrict__ emb,
                                                 float* __restrict__ out) {
    size_t e4 = (size_t)blockIdx.x * 256 + threadIdx.x;
    int b  = (int)(e4 >> 16);
    int d4 = (int)(e4 & 63);
    float4 p0 = ((const float4*)g_partAll[b][0])[d4];
    float4 p1 = ((const float4*)g_partAll[b][1])[d4];
    float4 p2 = ((const float4*)g_partAll[b][2])[d4];
    float4 p3 = ((const float4*)g_partAll[b][3])[d4];
    const float kk = 0.5f / 1024.f;
    float4 v = ((const float4*)emb)[e4];
    v.x += (p0.x + p1.x + p2.x + p3.x) * kk;
    v.y += (p0.y + p1.y + p2.y + p3.y) * kk;
    v.z += (p0.z + p1.z + p2.z + p3.z) * kk;
    v.w += (p0.w + p1.w + p2.w + p3.w) * kk;
    ((float4*)out)[e4] = v;
}

// ---------------- K_z: z = cw * X_switch . M, 32x64 tiles, double-buffered --
__global__ void __launch_bounds__(256) k_z(const float* __restrict__ emb,
                                           const float* __restrict__ cwp) {
    int et = blockIdx.x, b = blockIdx.y, mt = blockIdx.z;
    int nsw = g_nsw[b];
    if (mt * 32 >= nsw) return;
    int tid = threadIdx.x;
    __shared__ float Xs[2][16][36];     // [buf][k][row]
    __shared__ float Ms[2][16][68];     // [buf][k][e]
    __shared__ const float* rp[32];
    if (tid < 32) {
        int slot = mt * 32 + tid;
        rp[tid] = emb + ((size_t)b * NS + g_sw_idx[b][(slot < nsw) ? slot : 0]) * ND;
    }
    __syncthreads();
    const int xrow = tid >> 3, xk = (tid & 7) * 2;
    const int mk = tid >> 4, me4 = (tid & 15) * 4;
    const int rg = tid >> 4, eg = tid & 15;     // out: 2 rows x 4 e per thread
    const float* xp = rp[xrow];

    // preload stage 0
    float2 xv = *(const float2*)(xp + xk);
    float4 mv = *(const float4*)&g_M[mk][et * 64 + me4];
    Xs[0][xk][xrow] = xv.x; Xs[0][xk + 1][xrow] = xv.y;
    *(float4*)&Ms[0][mk][me4] = mv;
    __syncthreads();

    unsigned long long acc2[2][2] = {{0ULL, 0ULL}, {0ULL, 0ULL}};
    for (int s = 0; s < 16; s++) {
        int cur = s & 1;
        if (s + 1 < 16) {
            int k0 = (s + 1) * 16;
            xv = *(const float2*)(xp + k0 + xk);
            mv = *(const float4*)&g_M[k0 + mk][et * 64 + me4];
        }
        #pragma unroll
        for (int k = 0; k < 16; k++) {
            float2 xf = *(const float2*)&Xs[cur][k][rg * 2];
            ulonglong2 m2 = *(const ulonglong2*)&Ms[cur][k][eg * 4];
            unsigned long long x0 = splat2(xf.x), x1 = splat2(xf.y);
            FMA2(acc2[0][0], x0, m2.x); FMA2(acc2[0][1], x0, m2.y);
            FMA2(acc2[1][0], x1, m2.x); FMA2(acc2[1][1], x1, m2.y);
        }
        if (s + 1 < 16) {
            int nb2 = cur ^ 1;
            Xs[nb2][xk][xrow] = xv.x; Xs[nb2][xk + 1][xrow] = xv.y;
            *(float4*)&Ms[nb2][mk][me4] = mv;
            __syncthreads();
        }
    }
    float cwv = *cwp;
    #pragma unroll
    for (int r = 0; r < 2; r++) {
        int slot = mt * 32 + rg * 2 + r;
        if (slot < nsw) {
            float2 a = u2f(acc2[r][0]), b2 = u2f(acc2[r][1]);
            float4 o = make_float4(cwv * a.x, cwv * a.y, cwv * b2.x, cwv * b2.y);
            *(float4*)&g_z[b][slot][et * 64 + eg * 4] = o;
        }
    }
}

// ---------------- K_attn: fused scores + online softmax + V + epilogue ------
struct AttnSmem {
    float Esh[64][260];   // door-row emb tile
    float zsh[16][260];   // z rows for this i-tile
    float ssh[64][20];    // scores -> softmax weights (in place)
    float red[16][16];
    float uch[64];
    int   tj[64];
    float vch[16];
    float m[16];
    float dsum[16];
    float scale[16];
};

__global__ void __launch_bounds__(256) k_attn(const float* __restrict__ emb,
                                              float* __restrict__ out) {
    extern __shared__ char smraw[];
    AttnSmem* S = (AttnSmem*)smraw;
    int mt = blockIdx.x, b = blockIdx.y;
    int nsw = g_nsw[b];
    int i0 = mt * 16;
    if (i0 >= nsw) return;
    int nd = g_ndr[b];
    int tid = threadIdx.x;
    int ni = min(16, nsw - i0);

    for (int idx = tid; idx < 16 * 64; idx += 256) {
        int i = idx >> 6, q = idx & 63;
        float4 v = (i < ni) ? ((const float4*)&g_z[b][i0 + i][0])[q]
                            : make_float4(0.f, 0.f, 0.f, 0.f);
        *(float4*)&S->zsh[i][q * 4] = v;
    }
    if (tid < 16) {
        S->vch[tid]  = (tid < ni) ? g_vc[b][i0 + tid] : -1e30f;
        S->m[tid]    = (nd < NS) ? 0.f : -1e30f;
        S->dsum[tid] = 0.f;
    }
    unsigned long long accp[8];
    #pragma unroll
    for (int p = 0; p < 8; p++) accp[p] = 0ULL;

    const int il = tid & 15, jg = tid >> 4;

    for (int jb = 0; jb < nd; jb += 64) {
        int cnt = min(64, nd - jb);
        __syncthreads();
        if (tid < 64) {
            S->tj[tid]  = g_dr_idx[b][(tid < cnt) ? (jb + tid) : jb];
            S->uch[tid] = (tid < cnt) ? g_uc[b][jb + tid] : 0.f;
        }
        __syncthreads();
        for (int idx = tid; idx < 64 * 64; idx += 256) {
            int j = idx >> 6, q = idx & 63;
            float4 v = ((const float4*)&emb[((size_t)b * NS + S->tj[j]) * ND])[q];
            *(float4*)&S->Esh[j][q * 4] = v;
        }
        __syncthreads();
        // ---- scores (f32x2 packed over e): thread (il, jg) -> s[il][jg*4+q]
        float sv[4];
        {
            unsigned long long sA[4] = {0ULL, 0ULL, 0ULL, 0ULL};
            unsigned long long sB[4] = {0ULL, 0ULL, 0ULL, 0ULL};
            #pragma unroll 4
            for (int e = 0; e < ND; e += 4) {
                ulonglong2 z2 = *(const ulonglong2*)&S->zsh[il][e];
                #pragma unroll
                for (int q = 0; q < 4; q++) {
                    ulonglong2 e2 = *(const ulonglong2*)&S->Esh[jg * 4 + q][e];
                    FMA2(sA[q], z2.x, e2.x);
                    FMA2(sB[q], z2.y, e2.y);
                }
            }
            float vci = S->vch[il];
            float lm = -1e30f;
            #pragma unroll
            for (int q = 0; q < 4; q++) {
                int j = jg * 4 + q;
                float2 a = u2f(sA[q]), b2 = u2f(sB[q]);
                float s = (a.x + a.y) + (b2.x + b2.y);
                sv[q] = (j < cnt) ? s + vci + S->uch[j] : -1e30f;
                S->ssh[j][il] = sv[q];
                lm = fmaxf(lm, sv[q]);
            }
            S->red[jg][il] = lm;
        }
        __syncthreads();
        if (tid < 16) {
            float mo = S->m[tid], mn = mo;
            #pragma unroll
            for (int g = 0; g < 16; g++) mn = fmaxf(mn, S->red[g][tid]);
            S->scale[tid] = __expf(mo - mn);
            S->m[tid] = mn;
        }
        __syncthreads();
        {
            float mi = S->m[il];
            float ls = 0.f;
            #pragma unroll
            for (int q = 0; q < 4; q++) {
                int j = jg * 4 + q;
                float w = __expf(sv[q] - mi);
                S->ssh[j][il] = w;
                ls += w;
            }
            S->red[jg][il] = ls;
        }
        __syncthreads();
        if (tid < 16) {
            float cs = 0.f;
            #pragma unroll
            for (int g = 0; g < 16; g++) cs += S->red[g][tid];
            S->dsum[tid] = S->dsum[tid] * S->scale[tid] + cs;
        }
        // ---- V accumulate (f32x2 packed over i): thread = d
        #pragma unroll
        for (int p = 0; p < 8; p++) {
            unsigned long long sp = pack2(S->scale[2 * p], S->scale[2 * p + 1]);
            accp[p] = MUL2(accp[p], sp);
        }
        #pragma unroll 2
        for (int j = 0; j < 64; j++) {
            unsigned long long ev2 = splat2(S->Esh[j][tid]);
            ulonglong2 wa = *(const ulonglong2*)&S->ssh[j][0];
            ulonglong2 wb = *(const ulonglong2*)&S->ssh[j][4];
            ulonglong2 wc = *(const ulonglong2*)&S->ssh[j][8];
            ulonglong2 wd = *(const ulonglong2*)&S->ssh[j][12];
            FMA2(accp[0], wa.x, ev2); FMA2(accp[1], wa.y, ev2);
            FMA2(accp[2], wb.x, ev2); FMA2(accp[3], wb.y, ev2);
            FMA2(accp[4], wc.x, ev2); FMA2(accp[5], wc.y, ev2);
            FMA2(accp[6], wd.x, ev2); FMA2(accp[7], wd.y, ev2);
        }
    }
    __syncthreads();
    float sndv = 0.f;
    #pragma unroll
    for (int c = 0; c < 4; c++) sndv += g_partAll[b][c][tid] - g_partDoor[b][c][tid];
    for (int i = 0; i < ni; i++) {
        float2 ap = u2f(accp[i >> 1]);
        float av = (i & 1) ? ap.y : ap.x;
        float em = __expf(-S->m[i]);
        float denom = (float)(NS - nd) * em + S->dsum[i];
        int srow = g_sw_idx[b][i0 + i];
        size_t o = ((size_t)b * NS + srow) * ND + tid;
        out[o] = emb[o] + 0.5f * ((em * sndv + av) / denom);
    }
}

// ---------------- launch ------------------------------------------------------
extern "C" void kernel_launch(void* const* d_in, const int* in_sizes, int n_in,
                              void* d_out, int out_size) {
    const float* emb = (const float*)d_in[0];
    const int*   s32 = (const int*)d_in[1];   // int32 or int64, detected per block
    const float* Wq  = (const float*)d_in[2];
    const float* bq  = (const float*)d_in[3];
    const float* Wk  = (const float*)d_in[4];
    const float* bk  = (const float*)d_in[5];
    const float* cw  = (const float*)d_in[6];
    // d_in[7] = causal_bias: cancels inside softmax, unused.
    float* out = (float*)d_out;

    cudaFuncSetAttribute(k_attn, cudaFuncAttributeMaxDynamicSharedMemorySize,
                         (int)sizeof(AttnSmem));

    k_M<<<65, 256>>>(Wq, Wk, bq, bk);
    k_prep<<<dim3(NB, 5), 1024>>>(s32, emb, cw);
    k_default<<<(NB * NS * (ND / 4)) / 256, 256>>>(emb, out);
    k_z<<<dim3(4, NB, 32), 256>>>(emb, cw);
    k_attn<<<dim3(64, NB), 256, sizeof(AttnSmem)>>>(emb, out);
}

// round 6
// speedup vs baseline: 1.0295x; 1.0295x over previous
#include <cuda_runtime.h>
#include <cuda_bf16.h>

#define NB 32
#define NS 1024
#define ND 256

typedef unsigned long long ull;

// ---------------- packed f32x2 helpers --------------------------------------
__device__ __forceinline__ void FMA2(ull& d, ull a, ull b) {
    asm("fma.rn.f32x2 %0, %1, %2, %0;" : "+l"(d) : "l"(a), "l"(b));
}
__device__ __forceinline__ ull MUL2(ull a, ull b) {
    ull d;
    asm("mul.rn.f32x2 %0, %1, %2;" : "=l"(d) : "l"(a), "l"(b));
    return d;
}
__device__ __forceinline__ ull splat2(float v) {
    ull r;
    asm("mov.b64 %0, {%1, %1};" : "=l"(r) : "f"(v));
    return r;
}
__device__ __forceinline__ ull pack2(float x, float y) {
    ull r;
    asm("mov.b64 %0, {%1, %2};" : "=l"(r) : "f"(x), "f"(y));
    return r;
}
__device__ __forceinline__ float2 u2f(ull v) {
    float2 r;
    asm("mov.b64 {%0, %1}, %2;" : "=f"(r.x), "=f"(r.y) : "l"(v));
    return r;
}

// ---------------- scratch (static __device__, no allocation) ----------------
__device__ __align__(16) float g_M[ND][ND];     // M[d][e] = sum_a Wq[a][d]*Wk[a][e]
__device__ __align__(16) float g_vecA[ND];      // Wq^T bk
__device__ __align__(16) float g_vecB[ND];      // Wk^T bq
__device__ float g_c;                           // bq . bk
__device__ int   g_sw_idx[NB][NS];
__device__ int   g_dr_idx[NB][NS];
__device__ int   g_nsw[NB];
__device__ int   g_ndr[NB];
__device__ __align__(16) float g_partAll[NB][4][ND];
__device__ __align__(16) float g_partDoor[NB][4][ND];
__device__ __align__(16) float g_uc[NB][NS];    // cw*(x_t . vecB) per door slot
__device__ __align__(16) float g_vc[NB][NS];    // cw*(x_s . vecA + c) per switch slot
__device__ __align__(16) float g_z[NB][NS][ND]; // cw*(x_s . M) per switch slot

// ---------------- K_M: M = Wq^T Wk (32x32 tiles) + bias vectors + c ---------
__global__ void __launch_bounds__(256) k_M(const float* __restrict__ Wq,
                                           const float* __restrict__ Wk,
                                           const float* __restrict__ bq,
                                           const float* __restrict__ bk) {
    int tid = threadIdx.x;
    if (blockIdx.x == 64) {
        int d = tid;
        float va = 0.f, vb = 0.f;
        #pragma unroll 8
        for (int a = 0; a < ND; a++) {
            va += Wq[a * ND + d] * bk[a];
            vb += Wk[a * ND + d] * bq[a];
        }
        g_vecA[d] = va;
        g_vecB[d] = vb;
        if (tid < 32) {
            float c = 0.f;
            for (int i = tid; i < ND; i += 32) c += bq[i] * bk[i];
            #pragma unroll
            for (int o = 16; o; o >>= 1) c += __shfl_down_sync(0xFFFFFFFFu, c, o);
            if (tid == 0) g_c = c;
        }
        return;
    }
    int dt = blockIdx.x >> 3, et = blockIdx.x & 7;
    __shared__ float As[16][32], Bs[16][32];
    float a00 = 0.f, a01 = 0.f, a10 = 0.f, a11 = 0.f;
    int dg = tid >> 4, eg = tid & 15;
    int al = tid >> 4, c2 = (tid & 15) * 2;
    for (int a0 = 0; a0 < ND; a0 += 16) {
        *(float2*)&As[al][c2] = *(const float2*)&Wq[(a0 + al) * ND + dt * 32 + c2];
        *(float2*)&Bs[al][c2] = *(const float2*)&Wk[(a0 + al) * ND + et * 32 + c2];
        __syncthreads();
        #pragma unroll
        for (int k = 0; k < 16; k++) {
            float2 av = *(const float2*)&As[k][dg * 2];
            float2 bv = *(const float2*)&Bs[k][eg * 2];
            a00 += av.x * bv.x; a01 += av.x * bv.y;
            a10 += av.y * bv.x; a11 += av.y * bv.y;
        }
        __syncthreads();
    }
    int d = dt * 32 + dg * 2, e = et * 32 + eg * 2;
    g_M[d][e]     = a00; g_M[d][e + 1]     = a01;
    g_M[d + 1][e] = a10; g_M[d + 1][e + 1] = a11;
}

// ---------------- K_prep2: dtype detect + masks (bz0) | colsum (bz1..4) -----
__global__ void __launch_bounds__(1024) k_prep2(const int* __restrict__ s32,
                                                const float* __restrict__ emb) {
    int b = blockIdx.x, bz = blockIdx.y, tid = threadIdx.x;
    int vdet = (tid < 512) ? s32[b * NS + 2 * tid + 1] : 0;
    int is64 = !__syncthreads_or(vdet != 0);

    if (bz == 0) {
        int t = tid;
        int st = is64 ? s32[2 * (b * NS + t)] : s32[b * NS + t];
        int isw = (st == 3), idr = (st == 4 || st == 5);
        unsigned mw = __ballot_sync(0xFFFFFFFFu, isw);
        unsigned md = __ballot_sync(0xFFFFFFFFu, idr);
        int lane = t & 31, w = t >> 5;
        __shared__ int cw_[32], cd_[32], ow_[32], od_[32];
        if (lane == 0) { cw_[w] = __popc(mw); cd_[w] = __popc(md); }
        __syncthreads();
        if (tid == 0) {
            int aw = 0, ad = 0;
            for (int i = 0; i < 32; i++) {
                ow_[i] = aw; aw += cw_[i];
                od_[i] = ad; ad += cd_[i];
            }
            g_nsw[b] = aw; g_ndr[b] = ad;
        }
        __syncthreads();
        if (isw) g_sw_idx[b][ow_[w] + __popc(mw & ((1u << lane) - 1u))] = t;
        if (idr) g_dr_idx[b][od_[w] + __popc(md & ((1u << lane) - 1u))] = t;
    } else {
        int c = bz - 1, tg = tid >> 8, d = tid & 255;
        float sa = 0.f, sd = 0.f;
        int tb = c * 256 + tg * 64;
        #pragma unroll 4
        for (int i = 0; i < 64; i++) {
            int t = tb + i;
            float v = emb[((size_t)b * NS + t) * ND + d];
            int st = is64 ? s32[2 * (b * NS + t)] : s32[b * NS + t];
            sa += v;
            if (st == 4 || st == 5) sd += v;
        }
        __shared__ float psA[4][ND], psD[4][ND];
        psA[tg][d] = sa; psD[tg][d] = sd;
        __syncthreads();
        if (tid < ND) {
            float a = 0.f, dd = 0.f;
            #pragma unroll
            for (int g = 0; g < 4; g++) { a += psA[g][tid]; dd += psD[g][tid]; }
            g_partAll[b][c][tid]  = a;
            g_partDoor[b][c][tid] = dd;
        }
    }
}

// ---------------- K_uv: per-token bias dots (needs k_M + masks) -------------
__global__ void __launch_bounds__(512) k_uv(const float* __restrict__ emb,
                                            const float* __restrict__ cwp) {
    int b = blockIdx.x;
    int tid = threadIdx.x, lane = tid & 31, w = tid >> 5;   // 16 warps
    float cwv = *cwp, cval = g_c;
    int nd = g_ndr[b], nsw = g_nsw[b];
    for (int slot = w; slot < nd; slot += 16) {
        int tt = g_dr_idx[b][slot];
        const float4* er = (const float4*)&emb[((size_t)b * NS + tt) * ND];
        const float4* vr = (const float4*)g_vecB;
        float s = 0.f;
        #pragma unroll
        for (int j2 = 0; j2 < 2; j2++) {
            float4 e4 = er[lane + 32 * j2], v4 = vr[lane + 32 * j2];
            s += e4.x * v4.x + e4.y * v4.y + e4.z * v4.z + e4.w * v4.w;
        }
        #pragma unroll
        for (int o = 16; o; o >>= 1) s += __shfl_down_sync(0xFFFFFFFFu, s, o);
        if (lane == 0) g_uc[b][slot] = cwv * s;
    }
    for (int slot = w; slot < nsw; slot += 16) {
        int tt = g_sw_idx[b][slot];
        const float4* er = (const float4*)&emb[((size_t)b * NS + tt) * ND];
        const float4* vr = (const float4*)g_vecA;
        float s = 0.f;
        #pragma unroll
        for (int j2 = 0; j2 < 2; j2++) {
            float4 e4 = er[lane + 32 * j2], v4 = vr[lane + 32 * j2];
            s += e4.x * v4.x + e4.y * v4.y + e4.z * v4.z + e4.w * v4.w;
        }
        #pragma unroll
        for (int o = 16; o; o >>= 1) s += __shfl_down_sync(0xFFFFFFFFu, s, o);
        if (lane == 0) g_vc[b][slot] = cwv * (s + cval);
    }
}

// ---------------- K_default: out = emb + 0.5*colMean (all rows) -------------
__global__ void __launch_bounds__(256) k_default(const float* __restrict__ emb,
                                                 float* __restrict__ out) {
    size_t e4 = (size_t)blockIdx.x * 256 + threadIdx.x;
    int b  = (int)(e4 >> 16);
    int d4 = (int)(e4 & 63);
    float4 p0 = ((const float4*)g_partAll[b][0])[d4];
    float4 p1 = ((const float4*)g_partAll[b][1])[d4];
    float4 p2 = ((const float4*)g_partAll[b][2])[d4];
    float4 p3 = ((const float4*)g_partAll[b][3])[d4];
    const float kk = 0.5f / 1024.f;
    float4 v = ((const float4*)emb)[e4];
    v.x += (p0.x + p1.x + p2.x + p3.x) * kk;
    v.y += (p0.y + p1.y + p2.y + p3.y) * kk;
    v.z += (p0.z + p1.z + p2.z + p3.z) * kk;
    v.w += (p0.w + p1.w + p2.w + p3.w) * kk;
    ((float4*)out)[e4] = v;
}

// ---------------- K_z: z = cw * X_switch . M, 64x128 reg tiles --------------
// thread = 4 rows x 8 e; per k-step: 3 LDS.128 + 4 splats -> 16 FFMA2.
__global__ void __launch_bounds__(256) k_z(const float* __restrict__ emb,
                                           const float* __restrict__ cwp) {
    int et = blockIdx.x, b = blockIdx.y, mt = blockIdx.z;
    int nsw = g_nsw[b];
    if (mt * 64 >= nsw) return;
    int tid = threadIdx.x;
    __shared__ float Xs[2][16][68];     // [buf][k][row(64)+pad]
    __shared__ float Ms[2][16][132];    // [buf][k][e(128)+pad]
    __shared__ const float* rp[64];
    if (tid < 64) {
        int slot = mt * 64 + tid;
        rp[tid] = emb + ((size_t)b * NS + g_sw_idx[b][min(slot, nsw - 1)]) * ND;
    }
    __syncthreads();
    const int xrow = tid >> 2, xk4 = (tid & 3) * 4;   // X: 64 rows x 4 k-floats
    const int mkr = tid >> 5,  me4 = (tid & 31) * 4;  // M: k rows mkr,mkr+8 x 4 e
    const int rg = tid >> 4, eg = tid & 15;           // out: rows rg*4.., e eg*8..
    const float* xp = rp[xrow];
    const float* mp = &g_M[0][et * 128 + me4];

    float4 xv = *(const float4*)(xp + xk4);
    float4 ma = *(const float4*)(mp + (size_t)mkr * ND);
    float4 mb = *(const float4*)(mp + (size_t)(mkr + 8) * ND);
    Xs[0][xk4 + 0][xrow] = xv.x; Xs[0][xk4 + 1][xrow] = xv.y;
    Xs[0][xk4 + 2][xrow] = xv.z; Xs[0][xk4 + 3][xrow] = xv.w;
    *(float4*)&Ms[0][mkr][me4]     = ma;
    *(float4*)&Ms[0][mkr + 8][me4] = mb;
    __syncthreads();

    ull acc[4][4];
    #pragma unroll
    for (int r = 0; r < 4; r++)
        #pragma unroll
        for (int p = 0; p < 4; p++) acc[r][p] = 0ULL;

    for (int s = 0; s < 16; s++) {
        int cur = s & 1;
        if (s + 1 < 16) {
            int k0 = (s + 1) * 16;
            xv = *(const float4*)(xp + k0 + xk4);
            ma = *(const float4*)(mp + (size_t)(k0 + mkr) * ND);
            mb = *(const float4*)(mp + (size_t)(k0 + mkr + 8) * ND);
        }
        #pragma unroll
        for (int k = 0; k < 16; k++) {
            float4 xf = *(const float4*)&Xs[cur][k][rg * 4];
            ulonglong2 m0 = *(const ulonglong2*)&Ms[cur][k][eg * 8];
            ulonglong2 m1 = *(const ulonglong2*)&Ms[cur][k][eg * 8 + 4];
            ull x0 = splat2(xf.x), x1 = splat2(xf.y);
            ull x2 = splat2(xf.z), x3 = splat2(xf.w);
            FMA2(acc[0][0], x0, m0.x); FMA2(acc[0][1], x0, m0.y);
            FMA2(acc[0][2], x0, m1.x); FMA2(acc[0][3], x0, m1.y);
            FMA2(acc[1][0], x1, m0.x); FMA2(acc[1][1], x1, m0.y);
            FMA2(acc[1][2], x1, m1.x); FMA2(acc[1][3], x1, m1.y);
            FMA2(acc[2][0], x2, m0.x); FMA2(acc[2][1], x2, m0.y);
            FMA2(acc[2][2], x2, m1.x); FMA2(acc[2][3], x2, m1.y);
            FMA2(acc[3][0], x3, m0.x); FMA2(acc[3][1], x3, m0.y);
            FMA2(acc[3][2], x3, m1.x); FMA2(acc[3][3], x3, m1.y);
        }
        if (s + 1 < 16) {
            int nb2 = cur ^ 1;
            Xs[nb2][xk4 + 0][xrow] = xv.x; Xs[nb2][xk4 + 1][xrow] = xv.y;
            Xs[nb2][xk4 + 2][xrow] = xv.z; Xs[nb2][xk4 + 3][xrow] = xv.w;
            *(float4*)&Ms[nb2][mkr][me4]     = ma;
            *(float4*)&Ms[nb2][mkr + 8][me4] = mb;
            __syncthreads();
        }
    }
    float cwv = *cwp;
    #pragma unroll
    for (int r = 0; r < 4; r++) {
        int slot = mt * 64 + rg * 4 + r;
        if (slot < nsw) {
            float2 a0 = u2f(acc[r][0]), a1 = u2f(acc[r][1]);
            float2 a2 = u2f(acc[r][2]), a3 = u2f(acc[r][3]);
            float4 o0 = make_float4(cwv * a0.x, cwv * a0.y, cwv * a1.x, cwv * a1.y);
            float4 o1 = make_float4(cwv * a2.x, cwv * a2.y, cwv * a3.x, cwv * a3.y);
            *(float4*)&g_z[b][slot][et * 128 + eg * 8]     = o0;
            *(float4*)&g_z[b][slot][et * 128 + eg * 8 + 4] = o1;
        }
    }
}

// ---------------- K_attn: fused scores + online softmax + V + epilogue ------
struct AttnSmem {
    float Esh[64][260];
    float zsh[16][260];
    float ssh[64][20];
    float red[16][16];
    float uch[64];
    int   tj[64];
    float vch[16];
    float m[16];
    float dsum[16];
    float scale[16];
};

__global__ void __launch_bounds__(256) k_attn(const float* __restrict__ emb,
                                              float* __restrict__ out) {
    extern __shared__ char smraw[];
    AttnSmem* S = (AttnSmem*)smraw;
    int mt = blockIdx.x, b = blockIdx.y;
    int nsw = g_nsw[b];
    int i0 = mt * 16;
    if (i0 >= nsw) return;
    int nd = g_ndr[b];
    int tid = threadIdx.x;
    int ni = min(16, nsw - i0);

    for (int idx = tid; idx < 16 * 64; idx += 256) {
        int i = idx >> 6, q = idx & 63;
        float4 v = (i < ni) ? ((const float4*)&g_z[b][i0 + i][0])[q]
                            : make_float4(0.f, 0.f, 0.f, 0.f);
        *(float4*)&S->zsh[i][q * 4] = v;
    }
    if (tid < 16) {
        S->vch[tid]  = (tid < ni) ? g_vc[b][i0 + tid] : -1e30f;
        S->m[tid]    = (nd < NS) ? 0.f : -1e30f;
        S->dsum[tid] = 0.f;
    }
    ull accp[8];
    #pragma unroll
    for (int p = 0; p < 8; p++) accp[p] = 0ULL;

    const int il = tid & 15, jg = tid >> 4;

    for (int jb = 0; jb < nd; jb += 64) {
        int cnt = min(64, nd - jb);
        __syncthreads();
        if (tid < 64) {
            S->tj[tid]  = g_dr_idx[b][(tid < cnt) ? (jb + tid) : jb];
            S->uch[tid] = (tid < cnt) ? g_uc[b][jb + tid] : 0.f;
        }
        __syncthreads();
        for (int idx = tid; idx < 64 * 64; idx += 256) {
            int j = idx >> 6, q = idx & 63;
            float4 v = ((const float4*)&emb[((size_t)b * NS + S->tj[j]) * ND])[q];
            *(float4*)&S->Esh[j][q * 4] = v;
        }
        __syncthreads();
        float sv[4];
        {
            ull sA[4] = {0ULL, 0ULL, 0ULL, 0ULL};
            ull sB[4] = {0ULL, 0ULL, 0ULL, 0ULL};
            #pragma unroll 4
            for (int e = 0; e < ND; e += 4) {
                ulonglong2 z2 = *(const ulonglong2*)&S->zsh[il][e];
                #pragma unroll
                for (int q = 0; q < 4; q++) {
                    ulonglong2 e2 = *(const ulonglong2*)&S->Esh[jg * 4 + q][e];
                    FMA2(sA[q], z2.x, e2.x);
                    FMA2(sB[q], z2.y, e2.y);
                }
            }
            float vci = S->vch[il];
            float lm = -1e30f;
            #pragma unroll
            for (int q = 0; q < 4; q++) {
                int j = jg * 4 + q;
                float2 a = u2f(sA[q]), b2 = u2f(sB[q]);
                float s = (a.x + a.y) + (b2.x + b2.y);
                sv[q] = (j < cnt) ? s + vci + S->uch[j] : -1e30f;
                lm = fmaxf(lm, sv[q]);
            }
            S->red[jg][il] = lm;
        }
        __syncthreads();
        if (tid < 16) {
            float mo = S->m[tid], mn = mo;
            #pragma unroll
            for (int g = 0; g < 16; g++) mn = fmaxf(mn, S->red[g][tid]);
            S->scale[tid] = __expf(mo - mn);
            S->m[tid] = mn;
        }
        __syncthreads();
        {
            float mi = S->m[il];
            float ls = 0.f;
            #pragma unroll
            for (int q = 0; q < 4; q++) {
                int j = jg * 4 + q;
                float w = __expf(sv[q] - mi);
                S->ssh[j][il] = w;
                ls += w;
            }
            S->red[jg][il] = ls;
        }
        __syncthreads();
        if (tid < 16) {
            float cs = 0.f;
            #pragma unroll
            for (int g = 0; g < 16; g++) cs += S->red[g][tid];
            S->dsum[tid] = S->dsum[tid] * S->scale[tid] + cs;
        }
        #pragma unroll
        for (int p = 0; p < 8; p++) {
            ull sp = pack2(S->scale[2 * p], S->scale[2 * p + 1]);
            accp[p] = MUL2(accp[p], sp);
        }
        #pragma unroll 2
        for (int j = 0; j < 64; j++) {
            ull ev2 = splat2(S->Esh[j][tid]);
            ulonglong2 wa = *(const ulonglong2*)&S->ssh[j][0];
            ulonglong2 wb = *(const ulonglong2*)&S->ssh[j][4];
            ulonglong2 wc = *(const ulonglong2*)&S->ssh[j][8];
            ulonglong2 wd = *(const ulonglong2*)&S->ssh[j][12];
            FMA2(accp[0], wa.x, ev2); FMA2(accp[1], wa.y, ev2);
            FMA2(accp[2], wb.x, ev2); FMA2(accp[3], wb.y, ev2);
            FMA2(accp[4], wc.x, ev2); FMA2(accp[5], wc.y, ev2);
            FMA2(accp[6], wd.x, ev2); FMA2(accp[7], wd.y, ev2);
        }
    }
    __syncthreads();
    float sndv = 0.f;
    #pragma unroll
    for (int c = 0; c < 4; c++) sndv += g_partAll[b][c][tid] - g_partDoor[b][c][tid];
    for (int i = 0; i < ni; i++) {
        float2 ap = u2f(accp[i >> 1]);
        float av = (i & 1) ? ap.y : ap.x;
        float em = __expf(-S->m[i]);
        float denom = (float)(NS - nd) * em + S->dsum[i];
        int srow = g_sw_idx[b][i0 + i];
        size_t o = ((size_t)b * NS + srow) * ND + tid;
        out[o] = emb[o] + 0.5f * ((em * sndv + av) / denom);
    }
}

// ---------------- launch: fork-join graph ------------------------------------
extern "C" void kernel_launch(void* const* d_in, const int* in_sizes, int n_in,
                              void* d_out, int out_size) {
    const float* emb = (const float*)d_in[0];
    const int*   s32 = (const int*)d_in[1];   // int32 or int64, detected per block
    const float* Wq  = (const float*)d_in[2];
    const float* bq  = (const float*)d_in[3];
    const float* Wk  = (const float*)d_in[4];
    const float* bk  = (const float*)d_in[5];
    const float* cw  = (const float*)d_in[6];
    // d_in[7] = causal_bias: cancels inside softmax, unused.
    float* out = (float*)d_out;

    static bool inited = false;
    static cudaStream_t s1, s2;
    static cudaEvent_t eFork, eM, eP, eUV, eD;
    if (!inited) {
        cudaStreamCreateWithFlags(&s1, cudaStreamNonBlocking);
        cudaStreamCreateWithFlags(&s2, cudaStreamNonBlocking);
        cudaEventCreateWithFlags(&eFork, cudaEventDisableTiming);
        cudaEventCreateWithFlags(&eM,    cudaEventDisableTiming);
        cudaEventCreateWithFlags(&eP,    cudaEventDisableTiming);
        cudaEventCreateWithFlags(&eUV,   cudaEventDisableTiming);
        cudaEventCreateWithFlags(&eD,    cudaEventDisableTiming);
        cudaFuncSetAttribute(k_attn, cudaFuncAttributeMaxDynamicSharedMemorySize,
                             (int)sizeof(AttnSmem));
        inited = true;
    }

    // fork side streams into the (possibly capturing) main stream
    cudaEventRecord(eFork, 0);
    cudaStreamWaitEvent(s1, eFork, 0);
    cudaStreamWaitEvent(s2, eFork, 0);

    // stage 1: k_M (main) || k_prep2 (s1)
    k_M<<<65, 256>>>(Wq, Wk, bq, bk);
    cudaEventRecord(eM, 0);
    k_prep2<<<dim3(NB, 5), 1024, 0, s1>>>(s32, emb);
    cudaEventRecord(eP, s1);

    // stage 2: k_z (main, needs M + masks) || k_uv (s1, needs M + masks)
    //          || k_default (s2, needs colsums)
    cudaStreamWaitEvent(0, eP, 0);
    k_z<<<dim3(2, NB, 16), 256>>>(emb, cw);
    cudaStreamWaitEvent(s1, eM, 0);
    k_uv<<<NB, 512, 0, s1>>>(emb, cw);
    cudaEventRecord(eUV, s1);
    cudaStreamWaitEvent(s2, eP, 0);
    k_default<<<(NB * NS * (ND / 4)) / 256, 256, 0, s2>>>(emb, out);
    cudaEventRecord(eD, s2);

    // stage 3: k_attn (main, needs everything; overwrites switch rows of out)
    cudaStreamWaitEvent(0, eUV, 0);
    cudaStreamWaitEvent(0, eD, 0);
    k_attn<<<dim3(64, NB), 256, sizeof(AttnSmem)>>>(emb, out);
}